// round 17
// baseline (speedup 1.0000x reference)
#include <cuda_runtime.h>
#include <cuda_bf16.h>
#include <cuda_fp16.h>
#include <cstdint>

#define NN 100000
#define NE 1600000

typedef unsigned long long ull;

// ---------------------------------------------------------------------------
// Device scratch (no runtime allocation allowed)
// ---------------------------------------------------------------------------
__device__ __half g_SRh[(size_t)NN * 256]; // fp16: [n][0:128]=S(+b1), [128:256]=R  (51.2 MB)
__device__ float g_deg[NN];                // raw degree (counted in node_deg_kernel)
__device__ ull   g_W1f[16 * 4 * 32];       // B1 tf32 frags: [j16][t4][lane32] {b0,b1}
__device__ ull   g_W2f[8 * 16 * 32];       // B2 tf32 frags: [j8][t16][lane32] {b0,b1}

// ---------------------------------------------------------------------------
// helpers
// ---------------------------------------------------------------------------
// tf32 mma m16n8k8: A 4 regs, B 2 regs, C 4 fp32
__device__ __forceinline__ void mmatf(float c[4], const uint32_t a[4],
                                      uint32_t b0, uint32_t b1) {
    asm volatile(
        "mma.sync.aligned.m16n8k8.row.col.f32.tf32.tf32.f32 "
        "{%0,%1,%2,%3},{%4,%5,%6,%7},{%8,%9},{%0,%1,%2,%3};"
        : "+f"(c[0]), "+f"(c[1]), "+f"(c[2]), "+f"(c[3])
        : "r"(a[0]), "r"(a[1]), "r"(a[2]), "r"(a[3]), "r"(b0), "r"(b1));
}
__device__ __forceinline__ uint32_t tf32c(float x) {
    uint32_t r; asm("cvt.rna.tf32.f32 %0, %1;" : "=r"(r) : "f"(x)); return r;
}

// fp32x2 helpers for node-side kernels
__device__ __forceinline__ ull dup2(float x) { ull r; asm("mov.b64 %0,{%1,%1};" : "=l"(r) : "f"(x)); return r; }
__device__ __forceinline__ float2 up2(ull v) { float2 r; asm("mov.b64 {%0,%1},%2;" : "=f"(r.x), "=f"(r.y) : "l"(v)); return r; }
__device__ __forceinline__ ull fma2(ull a, ull b, ull c) { ull d; asm("fma.rn.f32x2 %0,%1,%2,%3;" : "=l"(d) : "l"(a), "l"(b), "l"(c)); return d; }

// L2 residency helpers
__device__ __forceinline__ ull mkpol_last() {
    ull p;
    asm("createpolicy.fractional.L2::evict_last.b64 %0, 1.0;" : "=l"(p));
    return p;
}
__device__ __forceinline__ float2 ldg_keep_h2(const __half* p, ull pol) {
    uint32_t v;
    asm volatile("ld.global.nc.L2::cache_hint.b32 %0, [%1], %2;"
                 : "=r"(v) : "l"(p), "l"(pol));
    return __half22float2(*(__half2*)&v);
}
__device__ __forceinline__ void stg_keep_h4(__half* p, uint32_t v0, uint32_t v1, ull pol) {
    asm volatile("st.global.L2::cache_hint.v2.b32 [%0], {%1,%2}, %3;"
                 :: "l"(p), "r"(v0), "r"(v1), "l"(pol) : "memory");
}

// hidden-dim slot permutation for GEMM2 A/k: physical slot p -> logical 2(p&3)+(p>>2)
__host__ __device__ __forceinline__ int sigma8(int p) { return 2 * (p & 3) + (p >> 2); }

// ---------------------------------------------------------------------------
// Merged init kernel: zero g_deg + build tf32 weight fragments
// W1 B-frag: n UNPERMUTED (logical hidden == physical C1 column).
// W2 B-frag: k-rows fetched at sigma8(physical slot) to match A2 renaming.
// ---------------------------------------------------------------------------
__global__ void init_kernel(const float* __restrict__ W1, const float* __restrict__ W2) {
    int idx = blockIdx.x * blockDim.x + threadIdx.x;
    if (idx < NN) g_deg[idx] = 0.0f;
    if (idx < 2048) {                        // W1c frags: [j16][t4][lane]
        int lane = idx & 31, fragid = idx >> 5;
        int t = fragid & 3, j = fragid >> 2;
        int col = j * 8 + (lane >> 2);                  // hidden col (NO perm)
        int k0  = t * 8 + (lane & 3);                   // input dim rows
        uint32_t b0 = tf32c(W1[(size_t)(128 + k0) * 128 + col]);
        uint32_t b1 = tf32c(W1[(size_t)(128 + k0 + 4) * 128 + col]);
        g_W1f[idx] = ((ull)b1 << 32) | b0;
    }
    if (idx < 4096) {                        // W2 frags: [j8][t16][lane]
        int lane = idx & 31, fragid = idx >> 5;
        int t = fragid & 15, j = fragid >> 4;
        int n = j * 8 + (lane >> 2);                    // out col (no perm)
        int kr0 = t * 8 + sigma8(lane & 3);             // slot q -> logical 2q
        int kr1 = t * 8 + sigma8(4 + (lane & 3));       // slot 4+q -> logical 2q+1
        uint32_t b0 = tf32c(W2[(size_t)kr0 * 64 + n]);
        uint32_t b1 = tf32c(W2[(size_t)kr1 * 64 + n]);
        g_W2f[idx] = ((ull)b1 << 32) | b0;
    }
}

// ---------------------------------------------------------------------------
// Fused node+degree kernel (single launch, roles by block id):
//   blocks [0, degB):        degree REDs over receivers (int4, grid-stride)
//   blocks [degB, degB+gn):  g_SRh(fp16) = nodes @ [W1a|W1b] (+b1), out = nodes@Wn+bn
// ---------------------------------------------------------------------------
__global__ void __launch_bounds__(256) node_deg_kernel(
    const float* __restrict__ A, const float* __restrict__ W1,
    const float* __restrict__ Wn, const float* __restrict__ b1,
    const float* __restrict__ bn, float* __restrict__ out,
    const int* __restrict__ recv, int degB, int M)
{
    if (blockIdx.x < degB) {
        int i0 = blockIdx.x * blockDim.x + threadIdx.x;
        int stride = degB * blockDim.x;
        for (int i = i0; i < NE / 4; i += stride) {
            int4 r4 = __ldcs(((const int4*)recv) + i);
            atomicAdd(&g_deg[r4.x], 1.0f);
            atomicAdd(&g_deg[r4.y], 1.0f);
            atomicAdd(&g_deg[r4.z], 1.0f);
            atomicAdd(&g_deg[r4.w], 1.0f);
        }
        return;
    }
    const int bx = blockIdx.x - degB;

    extern __shared__ float sm[];
    float* sAT = sm;               // [64][68]
    float* sB  = sm + 64 * 68;     // [64][320]
    const int tid = threadIdx.x;
    const int n0  = bx * 64;
    const ull pol = mkpol_last();

#pragma unroll
    for (int j = 0; j < 4; j++) {
        int s = tid + j * 256;
        int row = s >> 4, k0 = (s & 15) << 2, gn = n0 + row;
        float4 v = make_float4(0.f, 0.f, 0.f, 0.f);
        if (gn < M) v = *(const float4*)(A + (size_t)gn * 64 + k0);
        sAT[(k0 + 0) * 68 + row] = v.x; sAT[(k0 + 1) * 68 + row] = v.y;
        sAT[(k0 + 2) * 68 + row] = v.z; sAT[(k0 + 3) * 68 + row] = v.w;
    }
#pragma unroll
    for (int j = 0; j < 20; j++) {
        int s  = tid + j * 256;
        int r  = s / 80;
        int c4 = (s % 80) * 4;
        const float* src;
        if (c4 < 128)       src = W1 + (size_t)r * 128 + c4;
        else if (c4 < 256)  src = W1 + (size_t)(64 + r) * 128 + (c4 - 128);
        else                src = Wn + (size_t)r * 64 + (c4 - 256);
        *(float4*)(sB + r * 320 + c4) = *(const float4*)src;
    }
    __syncthreads();

    const int ty = tid >> 4, tx = tid & 15;
    ull acc[4][5][2];
#pragma unroll
    for (int m = 0; m < 4; m++)
#pragma unroll
        for (int q = 0; q < 5; q++) { acc[m][q][0] = 0ull; acc[m][q][1] = 0ull; }

#pragma unroll 4
    for (int k = 0; k < 64; k++) {
        float4 a = *(const float4*)(sAT + k * 68 + ty * 4);
        ull aa[4] = {dup2(a.x), dup2(a.y), dup2(a.z), dup2(a.w)};
#pragma unroll
        for (int q = 0; q < 5; q++) {
            ulonglong2 b = *(const ulonglong2*)(sB + k * 320 + q * 64 + tx * 4);
#pragma unroll
            for (int m = 0; m < 4; m++) {
                acc[m][q][0] = fma2(aa[m], b.x, acc[m][q][0]);
                acc[m][q][1] = fma2(aa[m], b.y, acc[m][q][1]);
            }
        }
    }
    float4 bq[5];
#pragma unroll
    for (int q = 0; q < 5; q++) {
        if (q < 2)      bq[q] = *(const float4*)(b1 + q * 64 + tx * 4);
        else if (q < 4) bq[q] = make_float4(0.f, 0.f, 0.f, 0.f);
        else            bq[q] = *(const float4*)(bn + tx * 4);
    }
#pragma unroll
    for (int m = 0; m < 4; m++) {
        int gn = n0 + ty * 4 + m;
        if (gn < M) {
#pragma unroll
            for (int q = 0; q < 4; q++) {
                float2 u0 = up2(acc[m][q][0]), u1 = up2(acc[m][q][1]);
                __half2 p0 = __floats2half2_rn(u0.x + bq[q].x, u0.y + bq[q].y);
                __half2 p1 = __floats2half2_rn(u1.x + bq[q].z, u1.y + bq[q].w);
                stg_keep_h4(g_SRh + (size_t)gn * 256 + q * 64 + tx * 4,
                            *(uint32_t*)&p0, *(uint32_t*)&p1, pol);
            }
            float2 u0 = up2(acc[m][4][0]), u1 = up2(acc[m][4][1]);
            *(float4*)(out + (size_t)gn * 64 + tx * 4) =
                make_float4(u0.x + bq[4].x, u0.y + bq[4].y, u1.x + bq[4].z, u1.y + bq[4].w);
        }
    }
}

// ---------------------------------------------------------------------------
// Edge kernel: tf32 m16n8k8 1-term; A2 = register renaming of relu(C1+S+R).
// ---------------------------------------------------------------------------
#define N_CHUNKS (NE / 32)

__global__ void __launch_bounds__(128, 2) edge_kernel(
    const float* __restrict__ edges,
    const int*   __restrict__ senders,
    const int*   __restrict__ receivers,
    const float* __restrict__ b2,
    float*       __restrict__ out)
{
    extern __shared__ char smem[];
    ull*   sW1f = (ull*)smem;               // 16KB
    ull*   sW2f = (ull*)(smem + 16384);     // 32KB
    float* sE   = (float*)(smem + 49152);   // 4 warps x 32 x 36 floats

    const int tid  = threadIdx.x;
    const int w    = tid >> 5;
    const int lane = tid & 31;
    const ull pol  = mkpol_last();

    // stage weight fragments once per block
#pragma unroll
    for (int j = 0; j < 16; j++) sW1f[tid + j * 128] = g_W1f[tid + j * 128];
#pragma unroll
    for (int j = 0; j < 32; j++) sW2f[tid + j * 128] = g_W2f[tid + j * 128];
    __syncthreads();

    float* myE = sE + w * 32 * 36;
    const int gw     = blockIdx.x * 4 + w;
    const int stride = gridDim.x * 4;

    const int r   = lane >> 2;          // 0..7
    const int q   = lane & 3;           // 0..3
    const int c2x = q * 2;              // S/R col base within 8-col tile
    const int pb  = (lane >> 1) & 1;    // pair base selector
    const bool oddl = lane & 1;

    for (int chunk = gw; chunk < N_CHUNKS; chunk += stride) {
        const int e0 = chunk * 32;
        __syncwarp();
#pragma unroll
        for (int qq = 0; qq < 8; qq++) {
            int row = qq * 4 + (lane >> 3);
            int col = (lane & 7) * 4;
            *(float4*)(myE + row * 36 + col) =
                __ldcs((const float4*)(edges + (size_t)(e0 + row) * 32 + col));
        }
        const int snd = __ldcs(senders + e0 + lane);
        const int rcv = __ldcs(receivers + e0 + lane);
        const float ivl = 1.0f / fmaxf(g_deg[rcv], 1.0f);
        __syncwarp();

#pragma unroll
        for (int mt = 0; mt < 2; mt++) {
            const int mb = mt * 16;

            // ---- A1 tf32 fragments (4 k8-steps over input dim 32) ----
            uint32_t a1[4][4];
#pragma unroll
            for (int t = 0; t < 4; t++) {
                a1[t][0] = tf32c(myE[(mb + r) * 36 + t * 8 + q]);
                a1[t][1] = tf32c(myE[(mb + r + 8) * 36 + t * 8 + q]);
                a1[t][2] = tf32c(myE[(mb + r) * 36 + t * 8 + 4 + q]);
                a1[t][3] = tf32c(myE[(mb + r + 8) * 36 + t * 8 + 4 + q]);
            }

            const int s_r  = __shfl_sync(0xFFFFFFFFu, snd, mb + r);
            const int s_r8 = __shfl_sync(0xFFFFFFFFu, snd, mb + r + 8);
            const int r_r  = __shfl_sync(0xFFFFFFFFu, rcv, mb + r);
            const int r_r8 = __shfl_sync(0xFFFFFFFFu, rcv, mb + r + 8);
            const __half* Sr  = g_SRh + (size_t)s_r  * 256;
            const __half* Sr8 = g_SRh + (size_t)s_r8 * 256;
            const __half* Rr  = g_SRh + (size_t)r_r  * 256 + 128;
            const __half* Rr8 = g_SRh + (size_t)r_r8 * 256 + 128;

            // ---- GEMM1 (16 hidden tiles x 4 MMA) + epilogue -> A2 frags ----
            uint32_t a2[16][4];
#pragma unroll
            for (int t2 = 0; t2 < 16; t2++) {
                float c1[4] = {0.f, 0.f, 0.f, 0.f};
#pragma unroll
                for (int t = 0; t < 4; t++) {
                    ull b = sW1f[(t2 * 4 + t) * 32 + lane];
                    mmatf(c1, a1[t], (uint32_t)b, (uint32_t)(b >> 32));
                }
                // h = relu(c1 + S + R); c0/c1 = cols t2*8 + {2q, 2q+1} row r; c2/c3 row r+8
                float2 sv0 = ldg_keep_h2(Sr  + t2 * 8 + c2x, pol);
                float2 sv1 = ldg_keep_h2(Sr8 + t2 * 8 + c2x, pol);
                float2 rv0 = ldg_keep_h2(Rr  + t2 * 8 + c2x, pol);
                float2 rv1 = ldg_keep_h2(Rr8 + t2 * 8 + c2x, pol);
                // A2 renaming: slot q <- logical 2q (c0,c2), slot q+4 <- logical 2q+1 (c1,c3)
                a2[t2][0] = tf32c(fmaxf(c1[0] + sv0.x + rv0.x, 0.f));
                a2[t2][1] = tf32c(fmaxf(c1[2] + sv1.x + rv1.x, 0.f));
                a2[t2][2] = tf32c(fmaxf(c1[1] + sv0.y + rv0.y, 0.f));
                a2[t2][3] = tf32c(fmaxf(c1[3] + sv1.y + rv1.y, 0.f));
            }

            const float iv_e = __shfl_sync(0xFFFFFFFFu, ivl, mb + r);
            const float iv_o = __shfl_sync(0xFFFFFFFFu, ivl, mb + r + 8);
            const int   er   = oddl ? r_r8 : r_r;
            const float iv   = oddl ? iv_o : iv_e;
            float* outp = out + (size_t)er * 64 + pb * 4;

            // ---- GEMM2 (8 out tiles x 16 MMA) + epilogue2 scatter ----
#pragma unroll
            for (int j = 0; j < 8; j++) {
                float c2[4] = {0.f, 0.f, 0.f, 0.f};
#pragma unroll
                for (int t = 0; t < 16; t++) {
                    ull b = sW2f[(j * 16 + t) * 32 + lane];
                    mmatf(c2, a2[t], (uint32_t)b, (uint32_t)(b >> 32));
                }
                float x0 = __shfl_xor_sync(0xFFFFFFFFu, c2[0], 1);
                float x1 = __shfl_xor_sync(0xFFFFFFFFu, c2[1], 1);
                float x2 = __shfl_xor_sync(0xFFFFFFFFu, c2[2], 1);
                float x3 = __shfl_xor_sync(0xFFFFFFFFu, c2[3], 1);
                float v0, v1, v2, v3;
                if (!oddl) { v0 = c2[0]; v1 = c2[1]; v2 = x0; v3 = x1; }
                else       { v0 = x2;    v1 = x3;    v2 = c2[2]; v3 = c2[3]; }
                float4 bb = *(const float4*)(b2 + j * 8 + pb * 4);
                v0 = (v0 + bb.x) * iv;  v1 = (v1 + bb.y) * iv;
                v2 = (v2 + bb.z) * iv;  v3 = (v3 + bb.w) * iv;
                asm volatile("red.global.add.v4.f32 [%0], {%1,%2,%3,%4};"
                             :: "l"(outp + j * 8), "f"(v0), "f"(v1), "f"(v2), "f"(v3)
                             : "memory");
            }
        }
    }
}

// ---------------------------------------------------------------------------
// Launch
// ---------------------------------------------------------------------------
extern "C" void kernel_launch(void* const* d_in, const int* in_sizes, int n_in,
                              void* d_out, int out_size)
{
    const float* nodes     = (const float*)d_in[0];
    const float* edges     = (const float*)d_in[1];
    const int*   senders   = (const int*)d_in[2];
    const int*   receivers = (const int*)d_in[3];
    const float* W1        = (const float*)d_in[4];
    const float* b1        = (const float*)d_in[5];
    const float* W2        = (const float*)d_in[6];
    const float* b2        = (const float*)d_in[7];
    const float* Wn        = (const float*)d_in[8];
    const float* bn        = (const float*)d_in[9];
    float* out = (float*)d_out;

    const size_t sm_node = (64 * 68 + 64 * 320) * sizeof(float);   // 99,328 B
    const size_t sm_edge = 16384 + 32768 + 4 * 32 * 36 * sizeof(float);  // 67,584 B

    cudaFuncSetAttribute(node_deg_kernel,
                         cudaFuncAttributeMaxDynamicSharedMemorySize, (int)sm_node);
    cudaFuncSetAttribute(edge_kernel,
                         cudaFuncAttributeMaxDynamicSharedMemorySize, (int)sm_edge);

    init_kernel<<<(NN + 255) / 256, 256>>>(W1, W2);

    const int DEGB = 512;
    int gnodes = (NN + 63) / 64;
    node_deg_kernel<<<DEGB + gnodes, 256, sm_node>>>(
        nodes, W1, Wn, b1, bn, out, receivers, DEGB, NN);

    edge_kernel<<<304, 128, sm_edge>>>(edges, senders, receivers, b2, out);
}